// round 16
// baseline (speedup 1.0000x reference)
#include <cuda_runtime.h>
#include <cstdint>

#define B_   256
#define D_   784
#define H_   1024
#define T_   10
#define NCH  18
#define CHLEN 44

#define KNEG (-1.4426950408889634f)   // -log2(e)

typedef unsigned long long ull;

// ---------------- scratch ----------------
__device__ __align__(16) float  g_Wt[D_ * H_];          // (-log2e)*W^T [D][H] scalar (chunksum)
__device__ __align__(16) float2 g_Wt2[D_ * H_];         // duplicated (w,w) pairs (k_main)
__device__ __align__(16) float  g_Apre[NCH * B_ * H_];  // scaled chunk-start accumulators
__device__ __align__(16) ull    g_part[D_ * 4 * 8 * 320]; // partial logits [d][tile4][qh8][j5*64c]

// ---------------- helpers ----------------
__device__ __forceinline__ float ex2f(float x) {
    float y; asm("ex2.approx.f32 %0, %1;" : "=f"(y) : "f"(x)); return y;
}
__device__ __forceinline__ float rcpf(float x) {
    float y; asm("rcp.approx.f32 %0, %1;" : "=f"(y) : "f"(x)); return y;
}
__device__ __forceinline__ ull fma2_(ull a, ull b, ull c) {
    ull d; asm("fma.rn.f32x2 %0, %1, %2, %3;" : "=l"(d) : "l"(a), "l"(b), "l"(c)); return d;
}
__device__ __forceinline__ ull add2_(ull a, ull b) {
    ull d; asm("add.rn.f32x2 %0, %1, %2;" : "=l"(d) : "l"(a), "l"(b)); return d;
}
__device__ __forceinline__ ull pack2_(float lo, float hi) {
    ull d; asm("mov.b64 %0, {%1, %2};" : "=l"(d) : "f"(lo), "f"(hi)); return d;
}
__device__ __forceinline__ void unpack2_(ull v, float& lo, float& hi) {
    asm("mov.b64 {%0, %1}, %2;" : "=f"(lo), "=f"(hi) : "l"(v));
}
__device__ __forceinline__ void cp_async16(float* s, const float* g) {
    unsigned sa = (unsigned)__cvta_generic_to_shared(s);
    asm volatile("cp.async.ca.shared.global [%0], [%1], 16;\n" :: "r"(sa), "l"(g));
}
__device__ __forceinline__ void cp_commit() {
    asm volatile("cp.async.commit_group;\n" ::: "memory");
}

// ---------------- K1: transpose W -> scalar + duplicated ----------------
__global__ void k_transW(const float* __restrict__ W) {
    __shared__ float tile[32][33];
    int d = blockIdx.x * 32 + threadIdx.x;
    int h = blockIdx.y * 32 + threadIdx.y;
#pragma unroll
    for (int j = 0; j < 32; j += 8)
        if (d < D_) tile[threadIdx.y + j][threadIdx.x] = W[(h + j) * D_ + d] * KNEG;
    __syncthreads();
    int ho = blockIdx.y * 32 + threadIdx.x;
    int do_ = blockIdx.x * 32 + threadIdx.y;
#pragma unroll
    for (int j = 0; j < 32; j += 8)
        if (do_ + j < D_) {
            float v = tile[threadIdx.x][threadIdx.y + j];
            g_Wt [(do_ + j) * H_ + ho] = v;
            g_Wt2[(do_ + j) * H_ + ho] = make_float2(v, v);
        }
}

// ---------------- K2: chunk sums ----------------
__global__ __launch_bounds__(512) void k_chunksum(const int* __restrict__ x) {
    int bg = blockIdx.x;        // 0..31 (8 batches each)
    int k  = blockIdx.y;
    int i0 = k * CHLEN;
    int len = min(CHLEN, D_ - i0);
    __shared__ float xs2[CHLEN * 8];
    int tid = threadIdx.x;
    for (int idx = tid; idx < len * 8; idx += 512) {
        int j = idx >> 3, b = idx & 7;
        xs2[idx] = (float)x[(size_t)(bg * 8 + b) * D_ + i0 + j];
    }
    __syncthreads();
    int h0 = blockIdx.z * 512 + tid;
    float acc[8];
#pragma unroll
    for (int b = 0; b < 8; b++) acc[b] = 0.f;
    float wn1 = g_Wt[i0 * H_ + h0];
    float wn2 = (len > 1) ? g_Wt[(i0 + 1) * H_ + h0] : 0.f;
    for (int j = 0; j < len; j++) {
        float wv = wn1;
        wn1 = wn2;
        if (j + 2 < len) wn2 = g_Wt[(i0 + j + 2) * H_ + h0];
        const float* xr = &xs2[j * 8];
#pragma unroll
        for (int b = 0; b < 8; b++)
            acc[b] = fmaf(xr[b], wv, acc[b]);
    }
#pragma unroll
    for (int b = 0; b < 8; b++)
        g_Apre[(size_t)(k * B_ + bg * 8 + b) * H_ + h0] = acc[b];
}

// ---------------- K3: exclusive prefix (MLP=18) ----------------
__global__ void k_prefix(const float* __restrict__ c) {
    int idx = blockIdx.x * 256 + threadIdx.x;
    int b  = idx >> 9;
    int h0 = (idx & 511) * 2;
    float2 v[NCH];
#pragma unroll
    for (int k = 0; k < NCH; k++)
        v[k] = *(const float2*)&g_Apre[(size_t)(k * B_ + b) * H_ + h0];
    float2 acc = *(const float2*)&c[h0];
    acc.x *= KNEG; acc.y *= KNEG;
#pragma unroll
    for (int k = 0; k < NCH; k++) {
        *(float2*)&g_Apre[(size_t)(k * B_ + b) * H_ + h0] = acc;
        acc.x += v[k].x; acc.y += v[k].y;
    }
}

// ---------------- K4: main kernel (64 batches x 128 h per block; 16 h/warp) ----------------
// smem (floats): V 3*1280 ; Wdup 3*256 ; RED 2*5120
#define SM_V   0
#define SM_W   3840
#define SM_RED 4608
#define SM_FLOATS 14848     // 59392 B/block; x3 = 178176 <= 232448

__device__ __forceinline__ void stage(float* sm, int i, int srel, int hbase, int tid,
                                      const float* __restrict__ V) {
    const int bb = srel % 3;
    const float* vg = V + (size_t)i * (T_ * H_) + (size_t)hbase * T_;   // 1280 floats
    float* vs = sm + SM_V + bb * 1280;
    cp_async16(vs + tid * 4, vg + tid * 4);                     // [0,1024)
    if (tid < 64)
        cp_async16(vs + 1024 + tid * 4, vg + 1024 + tid * 4);   // [1024,1280)
    else if (tid < 128)
        cp_async16(sm + SM_W + bb * 256 + (tid - 64) * 4,
                   ((const float*)(g_Wt2 + (size_t)i * H_ + hbase)) + (tid - 64) * 4);
}

__device__ __forceinline__ void step_compute(float* sm, ull* a2, ull x2,
                                             int hl, int w, int L, int srel) {
    const float* Vp = sm + SM_V + (srel % 3) * 1280;
    const ulonglong2* Wq = (const ulonglong2*)(sm + SM_W + (srel % 3) * 256);

    ull accA[5], accB[5];
#pragma unroll
    for (int j = 0; j < 5; j++) { accA[j] = 0ull; accB[j] = 0ull; }

#pragma unroll
    for (int p = 0; p < 8; p++) {       // h-pair (he, he+1), he = hl + 2p (even)
        const int he = hl + 2 * p;
        const ull aE = a2[2 * p], aO = a2[2 * p + 1];
        float fE0, fE1, fO0, fO1;
        unpack2_(aE, fE0, fE1);
        unpack2_(aO, fO0, fO1);
        const float sE0 = rcpf(1.f + ex2f(fE0));
        const float sE1 = rcpf(1.f + ex2f(fE1));
        const float sO0 = rcpf(1.f + ex2f(fO0));
        const float sO1 = rcpf(1.f + ex2f(fO1));

        const ulonglong2 wp = Wq[(hl >> 1) + p];     // ((we,we),(wo,wo))
        a2[2 * p]     = fma2_(x2, wp.x, aE);
        a2[2 * p + 1] = fma2_(x2, wp.y, aO);

        const ulonglong2* vc = (const ulonglong2*)(Vp + he * T_);  // 80B, 16B aligned
        const ulonglong2 c0 = vc[0];   // t01_e, t23_e
        const ulonglong2 c1 = vc[1];   // t45_e, t67_e
        const ulonglong2 c2 = vc[2];   // t89_e, t01_o
        const ulonglong2 c3 = vc[3];   // t23_o, t45_o
        const ulonglong2 c4 = vc[4];   // t67_o, t89_o

        const ull SE0 = pack2_(sE0, sE0);
        const ull SO0 = pack2_(sO0, sO0);
        accA[0] = fma2_(SE0, c0.x, accA[0]);
        accA[1] = fma2_(SE0, c0.y, accA[1]);
        accA[2] = fma2_(SE0, c1.x, accA[2]);
        accA[3] = fma2_(SE0, c1.y, accA[3]);
        accA[4] = fma2_(SE0, c2.x, accA[4]);
        accA[0] = fma2_(SO0, c2.y, accA[0]);
        accA[1] = fma2_(SO0, c3.x, accA[1]);
        accA[2] = fma2_(SO0, c3.y, accA[2]);
        accA[3] = fma2_(SO0, c4.x, accA[3]);
        accA[4] = fma2_(SO0, c4.y, accA[4]);

        const ull SE1 = pack2_(sE1, sE1);
        const ull SO1 = pack2_(sO1, sO1);
        accB[0] = fma2_(SE1, c0.x, accB[0]);
        accB[1] = fma2_(SE1, c0.y, accB[1]);
        accB[2] = fma2_(SE1, c1.x, accB[2]);
        accB[3] = fma2_(SE1, c1.y, accB[3]);
        accB[4] = fma2_(SE1, c2.x, accB[4]);
        accB[0] = fma2_(SO1, c2.y, accB[0]);
        accB[1] = fma2_(SO1, c3.x, accB[1]);
        accB[2] = fma2_(SO1, c3.y, accB[2]);
        accB[3] = fma2_(SO1, c4.x, accB[3]);
        accB[4] = fma2_(SO1, c4.y, accB[4]);
    }

    float* red = sm + SM_RED + (srel & 1) * 5120;
#pragma unroll
    for (int j = 0; j < 5; j++) {
        *(ull*)(red + ((w * 5 + j) * 64 + L) * 2)      = accA[j];
        *(ull*)(red + ((w * 5 + j) * 64 + 32 + L) * 2) = accB[j];
    }
}

__device__ __forceinline__ void reduce_store(const float* sm, ull* gp, int sdone, int L) {
    const float* red = sm + SM_RED + (sdone & 1) * 5120;
#pragma unroll
    for (int j = 0; j < 5; j++)
#pragma unroll
        for (int p = 0; p < 2; p++) {
            const int col = p * 32 + L;
            ull s = *(const ull*)(red + ((0 * 5 + j) * 64 + col) * 2);
#pragma unroll
            for (int ww = 1; ww < 8; ww++)
                s = add2_(s, *(const ull*)(red + ((ww * 5 + j) * 64 + col) * 2));
            gp[j * 64 + col] = s;
        }
}

__global__ __launch_bounds__(256, 3) void k_main(const int* __restrict__ xi,
                                                 const float* __restrict__ V) {
    extern __shared__ float sm[];
    const int tid   = threadIdx.x;
    const int w     = tid >> 5;       // 0..7
    const int L     = tid & 31;
    const int tile  = blockIdx.x;     // 0..3  (64 batches)
    const int chunk = blockIdx.y;     // 0..NCH-1
    const int qh    = blockIdx.z;     // 0..7  (128 h)
    const int i0  = chunk * CHLEN;
    const int len = min(CHLEN, D_ - i0);
    const int hbase = qh * 128;
    const int hl  = w * 16;           // local h within eighth
    const int h0  = hbase + hl;

    // a2[u] = (A[b0][h0+u], A[b1][h0+u]); b0 = tile*64+L, b1 = b0+32
    ull a2[16];
    {
        const float* ap0 = g_Apre + ((size_t)(chunk * B_ + tile * 64 + L)) * H_ + h0;
        const float* ap1 = ap0 + (size_t)32 * H_;
#pragma unroll
        for (int g = 0; g < 4; g++) {
            float4 va = *(const float4*)(ap0 + 4 * g);
            float4 vb = *(const float4*)(ap1 + 4 * g);
            a2[4 * g + 0] = pack2_(va.x, vb.x);
            a2[4 * g + 1] = pack2_(va.y, vb.y);
            a2[4 * g + 2] = pack2_(va.z, vb.z);
            a2[4 * g + 3] = pack2_(va.w, vb.w);
        }
    }

    stage(sm, i0, 0, hbase, tid, V); cp_commit();
    if (len > 1) { stage(sm, i0 + 1, 1, hbase, tid, V); cp_commit(); }

    const int* xrow0 = xi + (size_t)(tile * 64 + L) * D_ + i0;
    const int* xrow1 = xrow0 + (size_t)32 * D_;
    float x0buf[2], x1buf[2];
    x0buf[0] = (float)__ldg(xrow0);     x1buf[0] = (float)__ldg(xrow1);
    x0buf[1] = (len > 1) ? (float)__ldg(xrow0 + 1) : 0.f;
    x1buf[1] = (len > 1) ? (float)__ldg(xrow1 + 1) : 0.f;

    for (int s = 0; s < len; s++) {
        if (s + 1 < len) asm volatile("cp.async.wait_group 1;\n" ::: "memory");
        else             asm volatile("cp.async.wait_group 0;\n" ::: "memory");
        __syncthreads();

        const ull x2 = pack2_(x0buf[s & 1], x1buf[s & 1]);
        if (s + 2 < len) {
            x0buf[s & 1] = (float)__ldg(xrow0 + s + 2);
            x1buf[s & 1] = (float)__ldg(xrow1 + s + 2);
            stage(sm, i0 + s + 2, s + 2, hbase, tid, V); cp_commit();
        }

        if (s >= 1 && w == ((s - 1) & 7)) {
            ull* gp = g_part + ((size_t)((i0 + s - 1) * 4 + tile) * 8 + qh) * 320;
            reduce_store(sm, gp, s - 1, L);
        }

        step_compute(sm, a2, x2, hl, w, L, s);
    }

    __syncthreads();
    if (w == ((len - 1) & 7)) {
        ull* gp = g_part + ((size_t)((i0 + len - 1) * 4 + tile) * 8 + qh) * 320;
        reduce_store(sm, gp, len - 1, L);
    }
}

// ---------------- K5: combine 8 eighths + bias + softmax, 8 d per block ----------------
__global__ __launch_bounds__(64) void k_softmax(const float* __restrict__ bias,
                                                float* __restrict__ out) {
    __shared__ float buf[64 * T_ * 8];    // [b][t][dd] = 20KB
    const int d0   = blockIdx.x * 8;      // 98 blocks
    const int tile = blockIdx.y;          // 0..3
    const int b    = threadIdx.x;         // 0..63
    for (int dd = 0; dd < 8; dd++) {
        const int d = d0 + dd;
        const ull* gp = g_part + ((size_t)(d * 4 + tile) * 8) * 320;
        ull v[5];
#pragma unroll
        for (int j = 0; j < 5; j++) v[j] = gp[j * 64 + b];
#pragma unroll
        for (int q = 1; q < 8; q++)
#pragma unroll
            for (int j = 0; j < 5; j++)
                v[j] = add2_(v[j], gp[q * 320 + j * 64 + b]);
        float l[T_];
#pragma unroll
        for (int j = 0; j < 5; j++) {
            unpack2_(v[j], l[2 * j], l[2 * j + 1]);
            l[2 * j]     += __ldg(bias + d * T_ + 2 * j);
            l[2 * j + 1] += __ldg(bias + d * T_ + 2 * j + 1);
        }
        float mx = l[0];
#pragma unroll
        for (int t = 1; t < T_; t++) mx = fmaxf(mx, l[t]);
        float e[T_]; float sum = 0.f;
#pragma unroll
        for (int t = 0; t < T_; t++) {
            e[t] = ex2f((l[t] - mx) * 1.4426950408889634f);
            sum += e[t];
        }
        const float r = rcpf(sum);
#pragma unroll
        for (int t = 0; t < T_; t++)
            buf[(b * T_ + t) * 8 + dd] = e[t] * r;
    }
    __syncthreads();
    // flush as float4 over dd
    const float4* bv = (const float4*)buf;
    for (int q = threadIdx.x; q < 64 * T_ * 2; q += 64) {
        const int bp   = q / 20;
        const int rr   = q - bp * 20;
        const int tt   = rr >> 1;
        const int half = rr & 1;
        *(float4*)(out + (size_t)(tile * 64 + bp) * (T_ * D_) + tt * D_ + d0 + half * 4) = bv[q];
    }
}

// ---------------- launch ----------------
extern "C" void kernel_launch(void* const* d_in, const int* in_sizes, int n_in,
                              void* d_out, int out_size) {
    const int*   x    = (const int*)d_in[0];
    const float* W    = (const float*)d_in[1];
    const float* c    = (const float*)d_in[2];
    const float* V    = (const float*)d_in[3];
    const float* bias = (const float*)d_in[4];
    float* out = (float*)d_out;

    static_assert(3 * SM_FLOATS * 4 <= 232448, "smem budget for 3 blocks/SM");
    cudaFuncSetAttribute(k_main, cudaFuncAttributeMaxDynamicSharedMemorySize,
                         SM_FLOATS * (int)sizeof(float));

    k_transW<<<dim3((D_ + 31) / 32, H_ / 32), dim3(32, 8)>>>(W);     // launch 1
    k_chunksum<<<dim3(32, NCH, 2), 512>>>(x);                        // launch 2
    k_prefix<<<(B_ * H_ / 2) / 256, 256>>>(c);                       // launch 3
    k_main<<<dim3(4, NCH, 8), 256, SM_FLOATS * (int)sizeof(float)>>>(x, V);  // launch 4 -> profiled
    k_softmax<<<dim3(D_ / 8, 4), 64>>>(bias, out);                   // launch 5
}

// round 17
// speedup vs baseline: 1.3434x; 1.3434x over previous
#include <cuda_runtime.h>
#include <cstdint>

#define B_   256
#define D_   784
#define H_   1024
#define T_   10
#define NCH  18
#define CHLEN 44

#define KNEG (-1.4426950408889634f)   // -log2(e)

typedef unsigned long long ull;

// ---------------- scratch ----------------
__device__ __align__(16) float g_Wt[D_ * H_];            // (-log2e)*W^T [D][H]
__device__ __align__(16) float g_Apre[NCH * B_ * H_];    // scaled chunk-start accumulators
__device__ __align__(16) ull   g_part[D_ * 4 * 4 * 320]; // partial logits [d][tile4][qh4][j5*64c]

// ---------------- helpers ----------------
__device__ __forceinline__ float ex2f(float x) {
    float y; asm("ex2.approx.f32 %0, %1;" : "=f"(y) : "f"(x)); return y;
}
__device__ __forceinline__ float rcpf(float x) {
    float y; asm("rcp.approx.f32 %0, %1;" : "=f"(y) : "f"(x)); return y;
}
__device__ __forceinline__ ull fma2_(ull a, ull b, ull c) {
    ull d; asm("fma.rn.f32x2 %0, %1, %2, %3;" : "=l"(d) : "l"(a), "l"(b), "l"(c)); return d;
}
__device__ __forceinline__ ull add2_(ull a, ull b) {
    ull d; asm("add.rn.f32x2 %0, %1, %2;" : "=l"(d) : "l"(a), "l"(b)); return d;
}
__device__ __forceinline__ ull pack2_(float lo, float hi) {
    ull d; asm("mov.b64 %0, {%1, %2};" : "=l"(d) : "f"(lo), "f"(hi)); return d;
}
__device__ __forceinline__ void unpack2_(ull v, float& lo, float& hi) {
    asm("mov.b64 {%0, %1}, %2;" : "=f"(lo), "=f"(hi) : "l"(v));
}
__device__ __forceinline__ void cp_async16(float* s, const float* g) {
    unsigned sa = (unsigned)__cvta_generic_to_shared(s);
    asm volatile("cp.async.ca.shared.global [%0], [%1], 16;\n" :: "r"(sa), "l"(g));
}
__device__ __forceinline__ void cp_commit() {
    asm volatile("cp.async.commit_group;\n" ::: "memory");
}

// ---------------- K1: transpose W [H][D] -> (-log2e)*Wt [D][H] ----------------
__global__ void k_transW(const float* __restrict__ W) {
    __shared__ float tile[32][33];
    int d = blockIdx.x * 32 + threadIdx.x;
    int h = blockIdx.y * 32 + threadIdx.y;
#pragma unroll
    for (int j = 0; j < 32; j += 8)
        if (d < D_) tile[threadIdx.y + j][threadIdx.x] = W[(h + j) * D_ + d] * KNEG;
    __syncthreads();
    int ho = blockIdx.y * 32 + threadIdx.x;
    int do_ = blockIdx.x * 32 + threadIdx.y;
#pragma unroll
    for (int j = 0; j < 32; j += 8)
        if (do_ + j < D_) g_Wt[(do_ + j) * H_ + ho] = tile[threadIdx.x][threadIdx.y + j];
}

// ---------------- K2: chunk sums (4 h/thread float4, FMA-dense) ----------------
__global__ __launch_bounds__(256) void k_chunksum(const int* __restrict__ x) {
    const int bg = blockIdx.x;        // 0..31 (8 batches each)
    const int k  = blockIdx.y;        // 0..17
    const int i0 = k * CHLEN;
    const int len = min(CHLEN, D_ - i0);
    __shared__ float xs2[CHLEN * 8];
    const int tid = threadIdx.x;
    for (int idx = tid; idx < len * 8; idx += 256) {
        int j = idx >> 3, b = idx & 7;
        xs2[idx] = (float)x[(size_t)(bg * 8 + b) * D_ + i0 + j];
    }
    __syncthreads();
    const int h0 = tid * 4;
    float4 acc[8];
#pragma unroll
    for (int b = 0; b < 8; b++) acc[b] = make_float4(0.f, 0.f, 0.f, 0.f);
    float4 wn1 = *(const float4*)&g_Wt[(size_t)i0 * H_ + h0];
    float4 wn2 = (len > 1) ? *(const float4*)&g_Wt[(size_t)(i0 + 1) * H_ + h0] : wn1;
    for (int j = 0; j < len; j++) {
        const float4 wv = wn1;
        wn1 = wn2;
        if (j + 2 < len) wn2 = *(const float4*)&g_Wt[(size_t)(i0 + j + 2) * H_ + h0];
        const float* xr = &xs2[j * 8];
#pragma unroll
        for (int b = 0; b < 8; b++) {
            const float xb = xr[b];
            acc[b].x = fmaf(xb, wv.x, acc[b].x);
            acc[b].y = fmaf(xb, wv.y, acc[b].y);
            acc[b].z = fmaf(xb, wv.z, acc[b].z);
            acc[b].w = fmaf(xb, wv.w, acc[b].w);
        }
    }
#pragma unroll
    for (int b = 0; b < 8; b++)
        *(float4*)&g_Apre[(size_t)(k * B_ + bg * 8 + b) * H_ + h0] = acc[b];
}

// ---------------- K3: exclusive prefix (MLP=18) ----------------
__global__ void k_prefix(const float* __restrict__ c) {
    int idx = blockIdx.x * 256 + threadIdx.x;
    int b  = idx >> 9;
    int h0 = (idx & 511) * 2;
    float2 v[NCH];
#pragma unroll
    for (int k = 0; k < NCH; k++)
        v[k] = *(const float2*)&g_Apre[(size_t)(k * B_ + b) * H_ + h0];
    float2 acc = *(const float2*)&c[h0];
    acc.x *= KNEG; acc.y *= KNEG;
#pragma unroll
    for (int k = 0; k < NCH; k++) {
        *(float2*)&g_Apre[(size_t)(k * B_ + b) * H_ + h0] = acc;
        acc.x += v[k].x; acc.y += v[k].y;
    }
}

// ---------------- K4: main kernel (round-10 verbatim: 64 b x 256 h, 32 h/warp) ----------------
#define SM_V   0                        // 3 * 2560 = 7680
#define SM_W   7680                     // 3 * 256  =  768
#define SM_RED 8448                     // 2 * 5120 = 10240
#define SM_FLOATS 18688                 // 74752 B; x2 blocks = 149504 B

__device__ __forceinline__ void stage(float* sm, int i, int srel, int hbase, int tid,
                                      const float* __restrict__ V) {
    const int bb = srel % 3;
    const float* vg = V + (size_t)i * (T_ * H_) + (size_t)hbase * T_;   // 2560 floats
    float* vs = sm + SM_V + bb * 2560;
    cp_async16(vs + tid * 4, vg + tid * 4);
    if (tid < 128) cp_async16(vs + (tid + 512) * 4, vg + (tid + 512) * 4);
    else if (tid < 192)
        cp_async16(sm + SM_W + bb * 256 + (tid - 128) * 4,
                   g_Wt + (size_t)i * H_ + hbase + (tid - 128) * 4);
    cp_async16(vs + (tid + 256) * 4, vg + (tid + 256) * 4);
}

__device__ __forceinline__ void step_compute(float* sm, ull* a2, ull x2,
                                             int hl, int w, int L, int srel) {
    const float* Vp = sm + SM_V + (srel % 3) * 2560;
    const float* Wp = sm + SM_W + (srel % 3) * 256;

    ull accA[5], accB[5];
#pragma unroll
    for (int j = 0; j < 5; j++) { accA[j] = 0ull; accB[j] = 0ull; }

    float sb0, sb1;
    {
        float f0, f1;
        unpack2_(a2[0], f0, f1);
        sb0 = rcpf(1.f + ex2f(f0));
        sb1 = rcpf(1.f + ex2f(f1));
    }

#pragma unroll
    for (int u = 0; u < 32; u++) {      // h = hbase + hl + u; a2[u] = (a_b0, a_b1)
        float nb0 = 0.f, nb1 = 0.f;
        if (u < 31) {
            float f0, f1;
            unpack2_(a2[u + 1], f0, f1);
            nb0 = rcpf(1.f + ex2f(f0));
            nb1 = rcpf(1.f + ex2f(f1));
        }
        const float wv = Wp[hl + u];
        a2[u] = fma2_(x2, pack2_(wv, wv), a2[u]);

        const float* vr = Vp + (hl + u) * T_;     // 40B rows, 8B aligned
        const ull s0 = pack2_(sb0, sb0);
        const ull s1 = pack2_(sb1, sb1);
#pragma unroll
        for (int j = 0; j < 5; j++) {
            const ull vv = *(const ull*)(vr + 2 * j);
            accA[j] = fma2_(s0, vv, accA[j]);
            accB[j] = fma2_(s1, vv, accB[j]);
        }
        sb0 = nb0; sb1 = nb1;
    }

    float* red = sm + SM_RED + (srel & 1) * 5120;
#pragma unroll
    for (int j = 0; j < 5; j++) {
        *(ull*)(red + ((w * 5 + j) * 64 + L) * 2)      = accA[j];
        *(ull*)(red + ((w * 5 + j) * 64 + 32 + L) * 2) = accB[j];
    }
}

__device__ __forceinline__ void reduce_store(const float* sm, ull* gp, int sdone, int L) {
    const float* red = sm + SM_RED + (sdone & 1) * 5120;
#pragma unroll
    for (int j = 0; j < 5; j++)
#pragma unroll
        for (int p = 0; p < 2; p++) {
            const int col = p * 32 + L;
            ull s = *(const ull*)(red + ((0 * 5 + j) * 64 + col) * 2);
#pragma unroll
            for (int ww = 1; ww < 8; ww++)
                s = add2_(s, *(const ull*)(red + ((ww * 5 + j) * 64 + col) * 2));
            gp[j * 64 + col] = s;
        }
}

__global__ __launch_bounds__(256, 2) void k_main(const int* __restrict__ xi,
                                                 const float* __restrict__ V) {
    extern __shared__ float sm[];
    const int tid   = threadIdx.x;
    const int w     = tid >> 5;       // 0..7
    const int L     = tid & 31;
    const int tile  = blockIdx.x;     // 0..3  (64 batches)
    const int chunk = blockIdx.y;     // 0..NCH-1
    const int qh    = blockIdx.z;     // 0..3  (256 h)
    const int i0  = chunk * CHLEN;
    const int len = min(CHLEN, D_ - i0);
    const int hbase = qh * 256;
    const int hl  = w * 32;           // local h within quarter
    const int h0  = hbase + hl;

    // a2[u] = (A[b0][h0+u], A[b1][h0+u]); b0 = tile*64+L, b1 = b0+32
    ull a2[32];
    {
        const float* ap0 = g_Apre + ((size_t)(chunk * B_ + tile * 64 + L)) * H_ + h0;
        const float* ap1 = ap0 + (size_t)32 * H_;
#pragma unroll
        for (int g = 0; g < 8; g++) {
            float4 va = *(const float4*)(ap0 + 4 * g);
            float4 vb = *(const float4*)(ap1 + 4 * g);
            a2[4 * g + 0] = pack2_(va.x, vb.x);
            a2[4 * g + 1] = pack2_(va.y, vb.y);
            a2[4 * g + 2] = pack2_(va.z, vb.z);
            a2[4 * g + 3] = pack2_(va.w, vb.w);
        }
    }

    stage(sm, i0, 0, hbase, tid, V); cp_commit();
    if (len > 1) { stage(sm, i0 + 1, 1, hbase, tid, V); cp_commit(); }

    const int* xrow0 = xi + (size_t)(tile * 64 + L) * D_ + i0;
    const int* xrow1 = xrow0 + (size_t)32 * D_;
    float x0buf[2], x1buf[2];
    x0buf[0] = (float)__ldg(xrow0);     x1buf[0] = (float)__ldg(xrow1);
    x0buf[1] = (len > 1) ? (float)__ldg(xrow0 + 1) : 0.f;
    x1buf[1] = (len > 1) ? (float)__ldg(xrow1 + 1) : 0.f;

    for (int s = 0; s < len; s++) {
        if (s + 1 < len) asm volatile("cp.async.wait_group 1;\n" ::: "memory");
        else             asm volatile("cp.async.wait_group 0;\n" ::: "memory");
        __syncthreads();

        const ull x2 = pack2_(x0buf[s & 1], x1buf[s & 1]);
        if (s + 2 < len) {
            x0buf[s & 1] = (float)__ldg(xrow0 + s + 2);
            x1buf[s & 1] = (float)__ldg(xrow1 + s + 2);
            stage(sm, i0 + s + 2, s + 2, hbase, tid, V); cp_commit();
        }

        if (s >= 1 && w == ((s - 1) & 7)) {
            ull* gp = g_part + ((size_t)((i0 + s - 1) * 4 + tile) * 4 + qh) * 320;
            reduce_store(sm, gp, s - 1, L);
        }

        step_compute(sm, a2, x2, hl, w, L, s);
    }

    __syncthreads();
    if (w == ((len - 1) & 7)) {
        ull* gp = g_part + ((size_t)((i0 + len - 1) * 4 + tile) * 4 + qh) * 320;
        reduce_store(sm, gp, len - 1, L);
    }
}

// ---------------- K5: combine quarters + bias + softmax, 8 d per block ----------------
__global__ __launch_bounds__(64) void k_softmax(const float* __restrict__ bias,
                                                float* __restrict__ out) {
    __shared__ float buf[64 * T_ * 8];    // [b][t][dd] = 20KB
    const int d0   = blockIdx.x * 8;      // 98 blocks
    const int tile = blockIdx.y;          // 0..3
    const int b    = threadIdx.x;         // 0..63
    for (int dd = 0; dd < 8; dd++) {
        const int d = d0 + dd;
        const ull* gp = g_part + ((size_t)(d * 4 + tile) * 4) * 320;
        ull v[5];
#pragma unroll
        for (int j = 0; j < 5; j++) v[j] = gp[j * 64 + b];
#pragma unroll
        for (int q = 1; q < 4; q++)
#pragma unroll
            for (int j = 0; j < 5; j++)
                v[j] = add2_(v[j], gp[q * 320 + j * 64 + b]);
        float l[T_];
#pragma unroll
        for (int j = 0; j < 5; j++) {
            unpack2_(v[j], l[2 * j], l[2 * j + 1]);
            l[2 * j]     += __ldg(bias + d * T_ + 2 * j);
            l[2 * j + 1] += __ldg(bias + d * T_ + 2 * j + 1);
        }
        float mx = l[0];
#pragma unroll
        for (int t = 1; t < T_; t++) mx = fmaxf(mx, l[t]);
        float e[T_]; float sum = 0.f;
#pragma unroll
        for (int t = 0; t < T_; t++) {
            e[t] = ex2f((l[t] - mx) * 1.4426950408889634f);
            sum += e[t];
        }
        const float r = rcpf(sum);
#pragma unroll
        for (int t = 0; t < T_; t++)
            buf[(b * T_ + t) * 8 + dd] = e[t] * r;
    }
    __syncthreads();
    // flush as float4 over dd
    const float4* bv = (const float4*)buf;
    for (int q = threadIdx.x; q < 64 * T_ * 2; q += 64) {
        const int bp   = q / 20;
        const int rr   = q - bp * 20;
        const int tt   = rr >> 1;
        const int half = rr & 1;
        *(float4*)(out + (size_t)(tile * 64 + bp) * (T_ * D_) + tt * D_ + d0 + half * 4) = bv[q];
    }
}

// ---------------- launch ----------------
extern "C" void kernel_launch(void* const* d_in, const int* in_sizes, int n_in,
                              void* d_out, int out_size) {
    const int*   x    = (const int*)d_in[0];
    const float* W    = (const float*)d_in[1];
    const float* c    = (const float*)d_in[2];
    const float* V    = (const float*)d_in[3];
    const float* bias = (const float*)d_in[4];
    float* out = (float*)d_out;

    static_assert(2 * SM_FLOATS * 4 <= 232448, "smem budget");
    cudaFuncSetAttribute(k_main, cudaFuncAttributeMaxDynamicSharedMemorySize,
                         SM_FLOATS * (int)sizeof(float));

    k_transW<<<dim3((D_ + 31) / 32, H_ / 32), dim3(32, 8)>>>(W);     // launch 1
    k_chunksum<<<dim3(32, NCH), 256>>>(x);                           // launch 2
    k_prefix<<<(B_ * H_ / 2) / 256, 256>>>(c);                       // launch 3
    k_main<<<dim3(4, NCH, 4), 256, SM_FLOATS * (int)sizeof(float)>>>(x, V);  // launch 4 -> profiled
    k_softmax<<<dim3(D_ / 8, 4), 64>>>(bias, out);                   // launch 5
}